// round 2
// baseline (speedup 1.0000x reference)
#include <cuda_runtime.h>
#include <math.h>

#define N      65536
#define BATCH  4
#define DIM    96
#define TOT    288     // 192 kv channels + 96 q channels
#define HEADS  2
#define CPH    48

// ---------------- scratch (static device globals; no allocs) ----------------
__device__ float g_P [BATCH * TOT * N];   // conv1x1 outputs  [b][288][N]
__device__ float g_DW[BATCH * TOT * N];   // dwconv outputs   [b][288][N]
__device__ float g_G  [BATCH * HEADS * CPH * CPH];
__device__ float g_qn2[BATCH * DIM];
__device__ float g_kn2[BATCH * DIM];
__device__ float g_M  [BATCH * DIM * DIM];

// ---------------- K0: zero the atomically-accumulated state ----------------
__global__ void zero_kernel() {
    int i = blockIdx.x * 256 + threadIdx.x;
    if (i < BATCH * HEADS * CPH * CPH) g_G[i] = 0.f;
    if (i < BATCH * DIM) { g_qn2[i] = 0.f; g_kn2[i] = 0.f; }
}

// ---------------- shared GEMM body: 96 outputs x 128 pixels, K=96 -----------
// Split-K into two 48-channel chunks so static smem stays at 42 KB
// (no cudaFuncSetAttribute / dynamic smem needed).
// Thread tile: 12 outputs x 4 pixels (float4). Block = 256 threads.
__device__ __forceinline__ void gemm96_body(
    const float* __restrict__ Wsrc,   // [96][96] row-major (this block's outputs)
    const float* __restrict__ Xb,     // X base: rows are N floats apart, 128-pixel window
    float* __restrict__ Ob)           // output base: rows are N floats apart
{
    __shared__ float Wt[96 * 48];     // 18 KB
    __shared__ float Xt[48 * 128];    // 24 KB
    int tid = threadIdx.x;
    int tx = tid & 31, ty = tid >> 5;

    float4 acc[12];
#pragma unroll
    for (int i = 0; i < 12; i++) acc[i] = make_float4(0.f, 0.f, 0.f, 0.f);

#pragma unroll
    for (int kk = 0; kk < 96; kk += 48) {
        for (int i = tid; i < 1152; i += 256) {            // 96x48 W chunk
            int o = i / 12, c4 = i % 12;
            *(float4*)(Wt + o * 48 + c4 * 4) =
                *(const float4*)(Wsrc + o * 96 + kk + c4 * 4);
        }
        for (int i = tid; i < 1536; i += 256) {            // 48x128 X chunk
            int r = i >> 5, c4 = i & 31;
            *(float4*)(Xt + r * 128 + c4 * 4) =
                *(const float4*)(Xb + (long)(kk + r) * N + c4 * 4);
        }
        __syncthreads();

        const float* wrow = Wt + ty * 12 * 48;
#pragma unroll 4
        for (int c = 0; c < 48; c++) {
            float4 xv = *(const float4*)(Xt + c * 128 + tx * 4);
#pragma unroll
            for (int i = 0; i < 12; i++) {
                float w = wrow[i * 48 + c];                // uniform per warp -> broadcast
                acc[i].x = fmaf(w, xv.x, acc[i].x);
                acc[i].y = fmaf(w, xv.y, acc[i].y);
                acc[i].z = fmaf(w, xv.z, acc[i].z);
                acc[i].w = fmaf(w, xv.w, acc[i].w);
            }
        }
        __syncthreads();
    }

    float* ob = Ob + (long)(ty * 12) * N + tx * 4;
#pragma unroll
    for (int i = 0; i < 12; i++)
        *(float4*)(ob + (long)i * N) = acc[i];
}

// conv1x1 from an input tensor into g_P at channel offset oBase.
// grid: (512 pixel tiles, yGroups, BATCH)
__global__ __launch_bounds__(256) void gemm_in(
    const float* __restrict__ W, const float* __restrict__ X, int oBase)
{
    const float* Wsrc = W + blockIdx.y * 9216;
    const float* Xb   = X + (long)blockIdx.z * DIM * N + blockIdx.x * 128;
    float* Ob = g_P + ((long)blockIdx.z * TOT + oBase + blockIdx.y * 96) * N
              + blockIdx.x * 128;
    gemm96_body(Wsrc, Xb, Ob);
}

// final: out = M[b] @ v, v = g_DW channels 96..191. grid: (512, 1, BATCH)
__global__ __launch_bounds__(256) void gemm_out(float* __restrict__ out)
{
    const float* Wsrc = g_M + (long)blockIdx.z * DIM * DIM;
    const float* Xb   = g_DW + ((long)blockIdx.z * TOT + DIM) * N + blockIdx.x * 128;
    float* Ob = out + (long)blockIdx.z * DIM * N + blockIdx.x * 128;
    gemm96_body(Wsrc, Xb, Ob);
}

// ---------------- K2: depthwise 3x3 (same, zero pad) + norm sumsq -----------
// grid (64 row-chunks, 288 channels, 4 batches), block 256.
__global__ __launch_bounds__(256) void dwconv_kernel(
    const float* __restrict__ kv_dw, const float* __restrict__ q_dw)
{
    int tid = threadIdx.x;
    int ch = blockIdx.y, b = blockIdx.z;
    int y0 = blockIdx.x * 4;
    const float* in  = g_P  + ((long)b * TOT + ch) * N;
    float*       out = g_DW + ((long)b * TOT + ch) * N;
    const float* wp = (ch < 192) ? (kv_dw + ch * 9) : (q_dw + (ch - 192) * 9);
    float w[9];
#pragma unroll
    for (int i = 0; i < 9; i++) w[i] = __ldg(wp + i);

    int ry = tid >> 6;
    int px = (tid & 63) * 4;
    int yy = y0 + ry;
    float o0 = 0.f, o1 = 0.f, o2 = 0.f, o3 = 0.f;
#pragma unroll
    for (int dy = -1; dy <= 1; dy++) {
        int ys = yy + dy;
        if (ys < 0 || ys > 255) continue;
        const float* r = in + ys * 256 + px;
        float4 c = *(const float4*)r;
        float lf = (px > 0)   ? r[-1] : 0.f;
        float rt = (px < 252) ? r[4]  : 0.f;
        float w0 = w[(dy + 1) * 3], w1 = w[(dy + 1) * 3 + 1], w2 = w[(dy + 1) * 3 + 2];
        o0 += w0 * lf  + w1 * c.x + w2 * c.y;
        o1 += w0 * c.x + w1 * c.y + w2 * c.z;
        o2 += w0 * c.y + w1 * c.z + w2 * c.w;
        o3 += w0 * c.z + w1 * c.w + w2 * rt;
    }
    *(float4*)(out + yy * 256 + px) = make_float4(o0, o1, o2, o3);

    // accumulate sum-of-squares for q / k channel norms
    float s = o0 * o0 + o1 * o1 + o2 * o2 + o3 * o3;
#pragma unroll
    for (int off = 16; off; off >>= 1) s += __shfl_down_sync(0xffffffffu, s, off);
    __shared__ float red[8];
    if ((tid & 31) == 0) red[tid >> 5] = s;
    __syncthreads();
    if (tid == 0) {
        float t = 0.f;
#pragma unroll
        for (int i = 0; i < 8; i++) t += red[i];
        if (ch < 96)        atomicAdd(&g_kn2[b * DIM + ch], t);
        else if (ch >= 192) atomicAdd(&g_qn2[b * DIM + ch - 192], t);
    }
}

// ---------------- K3: Gram matrix G[b][h] = q_raw @ k_raw^T (split-K) -------
// grid (32 pixel-chunks of 2048, heads, batch), block 256 (16x16 thread grid,
// 3x3 register tile).
__global__ __launch_bounds__(256) void gram_kernel()
{
    __shared__ float Qt[48 * 68];
    __shared__ float Kt[48 * 68];
    int tid = threadIdx.x;
    int b = blockIdx.z, h = blockIdx.y;
    int pix0 = blockIdx.x * 2048;
    const float* Qb = g_DW + ((long)b * TOT + 192 + h * CPH) * N;
    const float* Kb = g_DW + ((long)b * TOT + h * CPH) * N;

    float acc[3][3] = {};
    int tr = tid >> 4, tc = tid & 15;

    for (int t = 0; t < 32; t++) {
        int p0 = pix0 + t * 64;
        for (int i = tid; i < 768; i += 256) {
            int r = i >> 4, c4 = i & 15;
            *(float4*)(Qt + r * 68 + c4 * 4) = *(const float4*)(Qb + (long)r * N + p0 + c4 * 4);
            *(float4*)(Kt + r * 68 + c4 * 4) = *(const float4*)(Kb + (long)r * N + p0 + c4 * 4);
        }
        __syncthreads();
#pragma unroll 2
        for (int p = 0; p < 64; p += 4) {
            float4 q0 = *(float4*)(Qt + (tr * 3 + 0) * 68 + p);
            float4 q1 = *(float4*)(Qt + (tr * 3 + 1) * 68 + p);
            float4 q2 = *(float4*)(Qt + (tr * 3 + 2) * 68 + p);
            float4 k0 = *(float4*)(Kt + (tc * 3 + 0) * 68 + p);
            float4 k1 = *(float4*)(Kt + (tc * 3 + 1) * 68 + p);
            float4 k2 = *(float4*)(Kt + (tc * 3 + 2) * 68 + p);
            acc[0][0] += q0.x*k0.x + q0.y*k0.y + q0.z*k0.z + q0.w*k0.w;
            acc[0][1] += q0.x*k1.x + q0.y*k1.y + q0.z*k1.z + q0.w*k1.w;
            acc[0][2] += q0.x*k2.x + q0.y*k2.y + q0.z*k2.z + q0.w*k2.w;
            acc[1][0] += q1.x*k0.x + q1.y*k0.y + q1.z*k0.z + q1.w*k0.w;
            acc[1][1] += q1.x*k1.x + q1.y*k1.y + q1.z*k1.z + q1.w*k1.w;
            acc[1][2] += q1.x*k2.x + q1.y*k2.y + q1.z*k2.z + q1.w*k2.w;
            acc[2][0] += q2.x*k0.x + q2.y*k0.y + q2.z*k0.z + q2.w*k0.w;
            acc[2][1] += q2.x*k1.x + q2.y*k1.y + q2.z*k1.z + q2.w*k1.w;
            acc[2][2] += q2.x*k2.x + q2.y*k2.y + q2.z*k2.z + q2.w*k2.w;
        }
        __syncthreads();
    }
    float* Gp = g_G + (long)(b * HEADS + h) * CPH * CPH;
#pragma unroll
    for (int i = 0; i < 3; i++)
#pragma unroll
        for (int j = 0; j < 3; j++)
            atomicAdd(&Gp[(tr * 3 + i) * CPH + tc * 3 + j], acc[i][j]);
}

// ---------------- K4: normalize, 4x top-k softmax, fold proj into M ---------
// grid 8 = (b,h), block 256.  M[b] = proj_w @ blockdiag(Wc_h0, Wc_h1).
__global__ __launch_bounds__(256) void attn_kernel(
    const float* __restrict__ temp, const float* __restrict__ proj_w,
    const float* __restrict__ a1, const float* __restrict__ a2,
    const float* __restrict__ a3, const float* __restrict__ a4)
{
    int b = blockIdx.x >> 1;
    int h = blockIdx.x & 1;
    int tid = threadIdx.x;
    __shared__ float attnS[48 * 49];
    __shared__ float WcS[48 * 49];
    __shared__ float nqS[48], nkS[48];

    if (tid < 48) {
        nqS[tid] = fmaxf(sqrtf(g_qn2[b * DIM + h * CPH + tid]), 1e-12f);
        nkS[tid] = fmaxf(sqrtf(g_kn2[b * DIM + h * CPH + tid]), 1e-12f);
    }
    __syncthreads();

    float tp = temp[h];
    const float* Gp = g_G + (long)(b * HEADS + h) * CPH * CPH;
    for (int i = tid; i < 48 * 48; i += 256) {
        int c = i / 48, d = i % 48;
        attnS[c * 49 + d] = Gp[c * 48 + d] / (nqS[c] * nkS[d]) * tp;
    }
    __syncthreads();

    if (tid < 48) {
        const float* row = attnS + tid * 49;
        float mx = row[0];
        for (int d = 1; d < 48; d++) mx = fmaxf(mx, row[d]);
        float s0 = 0.f, s1 = 0.f, s2 = 0.f, s3 = 0.f;
        for (int d = 0; d < 48; d++) {
            float a = row[d];
            int r = 0;
            for (int dd = 0; dd < 48; dd++) r += (row[dd] > a);
            float e = expf(a - mx);
            if (r < 24) s0 += e;
            if (r < 32) s1 += e;
            if (r < 36) s2 += e;
            if (r < 38) s3 += e;
        }
        float f0 = a1[0] / s0, f1 = a2[0] / s1, f2 = a3[0] / s2, f3 = a4[0] / s3;
        for (int d = 0; d < 48; d++) {
            float a = row[d];
            int r = 0;
            for (int dd = 0; dd < 48; dd++) r += (row[dd] > a);
            float e = expf(a - mx);
            float wv = e * ((r < 24 ? f0 : 0.f) + (r < 32 ? f1 : 0.f)
                          + (r < 36 ? f2 : 0.f) + (r < 38 ? f3 : 0.f));
            WcS[tid * 49 + d] = wv;
        }
    }
    __syncthreads();

    // M[b][o][h*48+d] = sum_c proj_w[o][h*48+c] * Wc[c][d]
    for (int i = tid; i < 96 * 48; i += 256) {
        int o = i / 48, d = i % 48;
        float s = 0.f;
        const float* pw = proj_w + o * DIM + h * CPH;
        for (int c = 0; c < 48; c++) s += pw[c] * WcS[c * 49 + d];
        g_M[(long)(b * DIM + o) * DIM + h * CPH + d] = s;
    }
}

// --------------------------------- launch -----------------------------------
extern "C" void kernel_launch(void* const* d_in, const int* in_sizes, int n_in,
                              void* d_out, int out_size)
{
    const float* x      = (const float*)d_in[0];
    const float* y      = (const float*)d_in[1];
    const float* temp   = (const float*)d_in[2];
    const float* kv_w   = (const float*)d_in[3];
    const float* kv_dw  = (const float*)d_in[4];
    const float* q_w    = (const float*)d_in[5];
    const float* q_dw   = (const float*)d_in[6];
    const float* proj_w = (const float*)d_in[7];
    const float* a1     = (const float*)d_in[8];
    const float* a2     = (const float*)d_in[9];
    const float* a3     = (const float*)d_in[10];
    const float* a4     = (const float*)d_in[11];
    float* out = (float*)d_out;

    zero_kernel<<<72, 256>>>();

    // conv1x1: kv = kv_w @ x (channels 0..191), q = q_w @ y (channels 192..287)
    gemm_in<<<dim3(512, 2, BATCH), 256>>>(kv_w, x, 0);
    gemm_in<<<dim3(512, 1, BATCH), 256>>>(q_w,  y, 192);

    // depthwise 3x3 on all 288 channels + q/k norm accumulation
    dwconv_kernel<<<dim3(64, TOT, BATCH), 256>>>(kv_dw, q_dw);

    // Gram matrices (split-K with atomics)
    gram_kernel<<<dim3(32, HEADS, BATCH), 256>>>();

    // tiny: normalize + top-k softmaxes + fold proj -> per-batch 96x96 M
    attn_kernel<<<8, 256>>>(temp, proj_w, a1, a2, a3, a4);

    // final = M @ v
    gemm_out<<<dim3(512, 1, BATCH), 256>>>(out);
}

// round 5
// speedup vs baseline: 1.1295x; 1.1295x over previous
#include <cuda_runtime.h>
#include <math.h>

#define N      65536
#define BATCH  4
#define DIM    96
#define TOT    288     // 192 kv channels + 96 q channels
#define HEADS  2
#define CPH    48

// ---------------- scratch (static device globals; no allocs) ----------------
__device__ float g_P [BATCH * TOT * N];   // conv1x1 outputs  [b][288][N]
__device__ float g_DW[BATCH * TOT * N];   // dwconv outputs   [b][288][N]
__device__ float g_G  [BATCH * HEADS * CPH * CPH];
__device__ float g_qn2[BATCH * DIM];
__device__ float g_kn2[BATCH * DIM];
__device__ float g_M  [BATCH * DIM * DIM];

// ---------------- K0: zero the atomically-accumulated state ----------------
__global__ void zero_kernel() {
    int i = blockIdx.x * 256 + threadIdx.x;
    if (i < BATCH * HEADS * CPH * CPH) g_G[i] = 0.f;
    if (i < BATCH * DIM) { g_qn2[i] = 0.f; g_kn2[i] = 0.f; }
}

// =====================  tf32x3 tensor-core GEMM  =============================
// C[96][128] += W[96][96] * X[96][128-pixel window], fp32-accurate via
// 3-term tf32 split:  A*B ~= Ah*Bh + Ah*Bl + Al*Bh  (err ~2^-22).
// Block: 256 threads = 8 warps in 2x4 grid; warp tile 48(M) x 32(N);
// per warp 3x4 m16n8k8 mma tiles.

__device__ __forceinline__ void mma_tf32(float* c, const unsigned* a, const unsigned* b) {
    asm volatile(
        "mma.sync.aligned.m16n8k8.row.col.f32.tf32.tf32.f32 "
        "{%0,%1,%2,%3}, {%4,%5,%6,%7}, {%8,%9}, {%0,%1,%2,%3};"
        : "+f"(c[0]), "+f"(c[1]), "+f"(c[2]), "+f"(c[3])
        : "r"(a[0]), "r"(a[1]), "r"(a[2]), "r"(a[3]), "r"(b[0]), "r"(b[1]));
}

__device__ __forceinline__ void split_tf32(float v, unsigned& hi, unsigned& lo) {
    asm("cvt.rna.tf32.f32 %0, %1;" : "=r"(hi) : "f"(v));
    float rem = v - __uint_as_float(hi);
    asm("cvt.rna.tf32.f32 %0, %1;" : "=r"(lo) : "f"(rem));
}

#define WS 104   // smem stride for W tiles  (q4*104 % 32 = 8*q4 -> conflict-free frags)
#define XS 136   // smem stride for X tiles  (q4*136 % 32 = 8*q4 -> conflict-free frags)

__device__ __forceinline__ void gemm_tc_body(
    const float* __restrict__ Wsrc,   // [96][96] row-major (this block's outputs)
    const float* __restrict__ Xb,     // X base: rows N floats apart, 128-px window
    float* __restrict__ Ob)           // O base: rows N floats apart
{
    __shared__ unsigned Wh[16 * WS], Wl[16 * WS];
    __shared__ unsigned Xh[16 * XS], Xl[16 * XS];

    int tid  = threadIdx.x;
    int lane = tid & 31, wid = tid >> 5;
    int warpM = wid >> 2, warpN = wid & 3;
    int m0 = warpM * 48, n0 = warpN * 32;
    int g = lane >> 2, q4 = lane & 3;

    float acc[3][4][4] = {};

    for (int kk = 0; kk < 96; kk += 16) {
        // --- stage W chunk [96 out][16 k] -> Wh/Wl[k][out] (transposed) ---
        for (int i = tid; i < 384; i += 256) {
            int o = i >> 2, j4 = i & 3;
            float4 w4 = *(const float4*)(Wsrc + o * 96 + kk + j4 * 4);
            unsigned h0,l0,h1,l1,h2,l2,h3,l3;
            split_tf32(w4.x, h0, l0); split_tf32(w4.y, h1, l1);
            split_tf32(w4.z, h2, l2); split_tf32(w4.w, h3, l3);
            int jb = j4 * 4;
            Wh[(jb+0)*WS + o] = h0; Wl[(jb+0)*WS + o] = l0;
            Wh[(jb+1)*WS + o] = h1; Wl[(jb+1)*WS + o] = l1;
            Wh[(jb+2)*WS + o] = h2; Wl[(jb+2)*WS + o] = l2;
            Wh[(jb+3)*WS + o] = h3; Wl[(jb+3)*WS + o] = l3;
        }
        // --- stage X chunk [16 k][128 px] -> Xh/Xl[k][px] ---
        for (int i = tid; i < 512; i += 256) {
            int r = i >> 5, c4 = i & 31;
            float4 x4 = *(const float4*)(Xb + (long)(kk + r) * N + c4 * 4);
            uint4 hv, lv;
            split_tf32(x4.x, hv.x, lv.x); split_tf32(x4.y, hv.y, lv.y);
            split_tf32(x4.z, hv.z, lv.z); split_tf32(x4.w, hv.w, lv.w);
            *(uint4*)(Xh + r * XS + c4 * 4) = hv;
            *(uint4*)(Xl + r * XS + c4 * 4) = lv;
        }
        __syncthreads();

#pragma unroll
        for (int kb = 0; kb < 16; kb += 8) {
            unsigned Ah[3][4], Al[3][4], Bh[4][2], Bl[4][2];
#pragma unroll
            for (int mi = 0; mi < 3; mi++) {
                int m = m0 + mi * 16 + g;
                int k0 = (kb + q4) * WS, k1 = (kb + q4 + 4) * WS;
                Ah[mi][0] = Wh[k0 + m]; Ah[mi][1] = Wh[k0 + m + 8];
                Ah[mi][2] = Wh[k1 + m]; Ah[mi][3] = Wh[k1 + m + 8];
                Al[mi][0] = Wl[k0 + m]; Al[mi][1] = Wl[k0 + m + 8];
                Al[mi][2] = Wl[k1 + m]; Al[mi][3] = Wl[k1 + m + 8];
            }
#pragma unroll
            for (int ni = 0; ni < 4; ni++) {
                int n = n0 + ni * 8 + g;
                int k0 = (kb + q4) * XS, k1 = (kb + q4 + 4) * XS;
                Bh[ni][0] = Xh[k0 + n]; Bh[ni][1] = Xh[k1 + n];
                Bl[ni][0] = Xl[k0 + n]; Bl[ni][1] = Xl[k1 + n];
            }
#pragma unroll
            for (int mi = 0; mi < 3; mi++)
#pragma unroll
                for (int ni = 0; ni < 4; ni++) {
                    mma_tf32(acc[mi][ni], Ah[mi], Bh[ni]);
                    mma_tf32(acc[mi][ni], Ah[mi], Bl[ni]);
                    mma_tf32(acc[mi][ni], Al[mi], Bh[ni]);
                }
        }
        __syncthreads();
    }

    // --- epilogue: c0,c1 at (row, 2*q4), c2,c3 at (row+8, 2*q4) ---
#pragma unroll
    for (int mi = 0; mi < 3; mi++) {
        int row = m0 + mi * 16 + g;
#pragma unroll
        for (int ni = 0; ni < 4; ni++) {
            int col = n0 + ni * 8 + 2 * q4;
            *(float2*)(Ob + (long)row * N + col) =
                make_float2(acc[mi][ni][0], acc[mi][ni][1]);
            *(float2*)(Ob + (long)(row + 8) * N + col) =
                make_float2(acc[mi][ni][2], acc[mi][ni][3]);
        }
    }
}

// conv1x1 into g_P at channel offset oBase. grid (512, yGroups, BATCH)
__global__ __launch_bounds__(256) void gemm_in_tc(
    const float* __restrict__ W, const float* __restrict__ X, int oBase)
{
    const float* Wsrc = W + blockIdx.y * 9216;
    const float* Xb   = X + (long)blockIdx.z * DIM * N + blockIdx.x * 128;
    float* Ob = g_P + ((long)blockIdx.z * TOT + oBase + blockIdx.y * 96) * N
              + blockIdx.x * 128;
    gemm_tc_body(Wsrc, Xb, Ob);
}

// final: out = M[b] @ v, v = g_DW channels 96..191. grid (512, 1, BATCH)
__global__ __launch_bounds__(256) void gemm_out_tc(float* __restrict__ out)
{
    const float* Wsrc = g_M + (long)blockIdx.z * DIM * DIM;
    const float* Xb   = g_DW + ((long)blockIdx.z * TOT + DIM) * N + blockIdx.x * 128;
    float* Ob = out + (long)blockIdx.z * DIM * N + blockIdx.x * 128;
    gemm_tc_body(Wsrc, Xb, Ob);
}

// ---------------- K2: depthwise 3x3 (same, zero pad) + norm sumsq -----------
__global__ __launch_bounds__(256) void dwconv_kernel(
    const float* __restrict__ kv_dw, const float* __restrict__ q_dw)
{
    int tid = threadIdx.x;
    int ch = blockIdx.y, b = blockIdx.z;
    int y0 = blockIdx.x * 4;
    const float* in  = g_P  + ((long)b * TOT + ch) * N;
    float*       out = g_DW + ((long)b * TOT + ch) * N;
    const float* wp = (ch < 192) ? (kv_dw + ch * 9) : (q_dw + (ch - 192) * 9);
    float w[9];
#pragma unroll
    for (int i = 0; i < 9; i++) w[i] = __ldg(wp + i);

    int ry = tid >> 6;
    int px = (tid & 63) * 4;
    int yy = y0 + ry;
    float o0 = 0.f, o1 = 0.f, o2 = 0.f, o3 = 0.f;
#pragma unroll
    for (int dy = -1; dy <= 1; dy++) {
        int ys = yy + dy;
        if (ys < 0 || ys > 255) continue;
        const float* r = in + ys * 256 + px;
        float4 c = *(const float4*)r;
        float lf = (px > 0)   ? r[-1] : 0.f;
        float rt = (px < 252) ? r[4]  : 0.f;
        float w0 = w[(dy + 1) * 3], w1 = w[(dy + 1) * 3 + 1], w2 = w[(dy + 1) * 3 + 2];
        o0 += w0 * lf  + w1 * c.x + w2 * c.y;
        o1 += w0 * c.x + w1 * c.y + w2 * c.z;
        o2 += w0 * c.y + w1 * c.z + w2 * c.w;
        o3 += w0 * c.z + w1 * c.w + w2 * rt;
    }
    *(float4*)(out + yy * 256 + px) = make_float4(o0, o1, o2, o3);

    float s = o0 * o0 + o1 * o1 + o2 * o2 + o3 * o3;
#pragma unroll
    for (int off = 16; off; off >>= 1) s += __shfl_down_sync(0xffffffffu, s, off);
    __shared__ float red[8];
    if ((tid & 31) == 0) red[tid >> 5] = s;
    __syncthreads();
    if (tid == 0) {
        float t = 0.f;
#pragma unroll
        for (int i = 0; i < 8; i++) t += red[i];
        if (ch < 96)        atomicAdd(&g_kn2[b * DIM + ch], t);
        else if (ch >= 192) atomicAdd(&g_qn2[b * DIM + ch - 192], t);
    }
}

// ---------------- K3: Gram matrix G[b][h] = q_raw @ k_raw^T (split-K) -------
__global__ __launch_bounds__(256) void gram_kernel()
{
    __shared__ float Qt[48 * 68];
    __shared__ float Kt[48 * 68];
    int tid = threadIdx.x;
    int b = blockIdx.z, h = blockIdx.y;
    int pix0 = blockIdx.x * 2048;
    const float* Qb = g_DW + ((long)b * TOT + 192 + h * CPH) * N;
    const float* Kb = g_DW + ((long)b * TOT + h * CPH) * N;

    float acc[3][3] = {};
    int tr = tid >> 4, tc = tid & 15;

    for (int t = 0; t < 32; t++) {
        int p0 = pix0 + t * 64;
        for (int i = tid; i < 768; i += 256) {
            int r = i >> 4, c4 = i & 15;
            *(float4*)(Qt + r * 68 + c4 * 4) = *(const float4*)(Qb + (long)r * N + p0 + c4 * 4);
            *(float4*)(Kt + r * 68 + c4 * 4) = *(const float4*)(Kb + (long)r * N + p0 + c4 * 4);
        }
        __syncthreads();
#pragma unroll 2
        for (int p = 0; p < 64; p += 4) {
            float4 q0 = *(float4*)(Qt + (tr * 3 + 0) * 68 + p);
            float4 q1 = *(float4*)(Qt + (tr * 3 + 1) * 68 + p);
            float4 q2 = *(float4*)(Qt + (tr * 3 + 2) * 68 + p);
            float4 k0 = *(float4*)(Kt + (tc * 3 + 0) * 68 + p);
            float4 k1 = *(float4*)(Kt + (tc * 3 + 1) * 68 + p);
            float4 k2 = *(float4*)(Kt + (tc * 3 + 2) * 68 + p);
            acc[0][0] += q0.x*k0.x + q0.y*k0.y + q0.z*k0.z + q0.w*k0.w;
            acc[0][1] += q0.x*k1.x + q0.y*k1.y + q0.z*k1.z + q0.w*k1.w;
            acc[0][2] += q0.x*k2.x + q0.y*k2.y + q0.z*k2.z + q0.w*k2.w;
            acc[1][0] += q1.x*k0.x + q1.y*k0.y + q1.z*k0.z + q1.w*k0.w;
            acc[1][1] += q1.x*k1.x + q1.y*k1.y + q1.z*k1.z + q1.w*k1.w;
            acc[1][2] += q1.x*k2.x + q1.y*k2.y + q1.z*k2.z + q1.w*k2.w;
            acc[2][0] += q2.x*k0.x + q2.y*k0.y + q2.z*k0.z + q2.w*k0.w;
            acc[2][1] += q2.x*k1.x + q2.y*k1.y + q2.z*k1.z + q2.w*k1.w;
            acc[2][2] += q2.x*k2.x + q2.y*k2.y + q2.z*k2.z + q2.w*k2.w;
        }
        __syncthreads();
    }
    float* Gp = g_G + (long)(b * HEADS + h) * CPH * CPH;
#pragma unroll
    for (int i = 0; i < 3; i++)
#pragma unroll
        for (int j = 0; j < 3; j++)
            atomicAdd(&Gp[(tr * 3 + i) * CPH + tc * 3 + j], acc[i][j]);
}

// ---------------- K4: normalize, 4x top-k softmax, fold proj into M ---------
__global__ __launch_bounds__(256) void attn_kernel(
    const float* __restrict__ temp, const float* __restrict__ proj_w,
    const float* __restrict__ a1, const float* __restrict__ a2,
    const float* __restrict__ a3, const float* __restrict__ a4)
{
    int b = blockIdx.x >> 1;
    int h = blockIdx.x & 1;
    int tid = threadIdx.x;
    __shared__ float attnS[48 * 49];
    __shared__ float WcS[48 * 49];
    __shared__ float nqS[48], nkS[48];

    if (tid < 48) {
        nqS[tid] = fmaxf(sqrtf(g_qn2[b * DIM + h * CPH + tid]), 1e-12f);
        nkS[tid] = fmaxf(sqrtf(g_kn2[b * DIM + h * CPH + tid]), 1e-12f);
    }
    __syncthreads();

    float tp = temp[h];
    const float* Gp = g_G + (long)(b * HEADS + h) * CPH * CPH;
    for (int i = tid; i < 48 * 48; i += 256) {
        int c = i / 48, d = i % 48;
        attnS[c * 49 + d] = Gp[c * 48 + d] / (nqS[c] * nkS[d]) * tp;
    }
    __syncthreads();

    if (tid < 48) {
        const float* row = attnS + tid * 49;
        float mx = row[0];
        for (int d = 1; d < 48; d++) mx = fmaxf(mx, row[d]);
        float s0 = 0.f, s1 = 0.f, s2 = 0.f, s3 = 0.f;
        for (int d = 0; d < 48; d++) {
            float a = row[d];
            int r = 0;
            for (int dd = 0; dd < 48; dd++) r += (row[dd] > a);
            float e = expf(a - mx);
            if (r < 24) s0 += e;
            if (r < 32) s1 += e;
            if (r < 36) s2 += e;
            if (r < 38) s3 += e;
        }
        float f0 = a1[0] / s0, f1 = a2[0] / s1, f2 = a3[0] / s2, f3 = a4[0] / s3;
        for (int d = 0; d < 48; d++) {
            float a = row[d];
            int r = 0;
            for (int dd = 0; dd < 48; dd++) r += (row[dd] > a);
            float e = expf(a - mx);
            float wv = e * ((r < 24 ? f0 : 0.f) + (r < 32 ? f1 : 0.f)
                          + (r < 36 ? f2 : 0.f) + (r < 38 ? f3 : 0.f));
            WcS[tid * 49 + d] = wv;
        }
    }
    __syncthreads();

    for (int i = tid; i < 96 * 48; i += 256) {
        int o = i / 48, d = i % 48;
        float s = 0.f;
        const float* pw = proj_w + o * DIM + h * CPH;
        for (int c = 0; c < 48; c++) s += pw[c] * WcS[c * 49 + d];
        g_M[(long)(b * DIM + o) * DIM + h * CPH + d] = s;
    }
}

// --------------------------------- launch -----------------------------------
extern "C" void kernel_launch(void* const* d_in, const int* in_sizes, int n_in,
                              void* d_out, int out_size)
{
    const float* x      = (const float*)d_in[0];
    const float* y      = (const float*)d_in[1];
    const float* temp   = (const float*)d_in[2];
    const float* kv_w   = (const float*)d_in[3];
    const float* kv_dw  = (const float*)d_in[4];
    const float* q_w    = (const float*)d_in[5];
    const float* q_dw   = (const float*)d_in[6];
    const float* proj_w = (const float*)d_in[7];
    const float* a1     = (const float*)d_in[8];
    const float* a2     = (const float*)d_in[9];
    const float* a3     = (const float*)d_in[10];
    const float* a4     = (const float*)d_in[11];
    float* out = (float*)d_out;

    zero_kernel<<<72, 256>>>();

    // conv1x1 (tensor cores, tf32x3): kv from x (ch 0..191), q from y (ch 192..287)
    gemm_in_tc<<<dim3(512, 2, BATCH), 256>>>(kv_w, x, 0);
    gemm_in_tc<<<dim3(512, 1, BATCH), 256>>>(q_w,  y, 192);

    // depthwise 3x3 on all 288 channels + q/k norm accumulation
    dwconv_kernel<<<dim3(64, TOT, BATCH), 256>>>(kv_dw, q_dw);

    // Gram matrices (split-K with atomics, fp32)
    gram_kernel<<<dim3(32, HEADS, BATCH), 256>>>();

    // tiny: normalize + top-k softmaxes + fold proj -> per-batch 96x96 M
    attn_kernel<<<8, 256>>>(temp, proj_w, a1, a2, a3, a4);

    // final = M @ v (tensor cores)
    gemm_out_tc<<<dim3(512, 1, BATCH), 256>>>(out);
}

// round 8
// speedup vs baseline: 1.1734x; 1.0389x over previous
#include <cuda_runtime.h>
#include <cuda_bf16.h>
#include <math.h>

#define N      65536
#define BATCH  4
#define DIM    96
#define TOT    288     // 192 kv channels + 96 q channels
#define HEADS  2
#define CPH    48

// ---------------- scratch (static device globals; no allocs) ----------------
__device__ float g_P [BATCH * TOT * N];   // conv1x1 outputs  [b][288][N]
__device__ float g_DW[BATCH * TOT * N];   // dwconv outputs   [b][288][N]
__device__ float g_G  [BATCH * HEADS * CPH * CPH];
__device__ float g_qn2[BATCH * DIM];
__device__ float g_kn2[BATCH * DIM];
__device__ float g_M  [BATCH * DIM * DIM];

// ---------------- K0: zero the atomically-accumulated state ----------------
__global__ void zero_kernel() {
    int i = blockIdx.x * 256 + threadIdx.x;
    if (i < BATCH * HEADS * CPH * CPH) g_G[i] = 0.f;
    if (i < BATCH * DIM) { g_qn2[i] = 0.f; g_kn2[i] = 0.f; }
}

// =====================  bf16x3 tensor-core GEMM  =============================
// C[96][128] += W[96][96] * X[96][128-px window], near-fp32 via 3-term bf16
// split: A*B ~= Ah*Bh + Ah*Bl + Al*Bh  (residual ~2^-18).
// Block: 256 threads = 8 warps (2x4); warp tile 48(M) x 32(N);
// mma.m16n8k16.bf16: one k-step covers a whole 16-k chunk.

__device__ __forceinline__ void mma_bf16(float* c, const unsigned* a, const unsigned* b) {
    asm volatile(
        "mma.sync.aligned.m16n8k16.row.col.f32.bf16.bf16.f32 "
        "{%0,%1,%2,%3}, {%4,%5,%6,%7}, {%8,%9}, {%0,%1,%2,%3};"
        : "+f"(c[0]), "+f"(c[1]), "+f"(c[2]), "+f"(c[3])
        : "r"(a[0]), "r"(a[1]), "r"(a[2]), "r"(a[3]), "r"(b[0]), "r"(b[1]));
}

__device__ __forceinline__ void split_bf16(float v, unsigned short& h, unsigned short& l) {
    __nv_bfloat16 bh = __float2bfloat16(v);           // rn
    float r = v - __bfloat162float(bh);               // exact
    __nv_bfloat16 bl = __float2bfloat16(r);
    h = __bfloat16_as_ushort(bh);
    l = __bfloat16_as_ushort(bl);
}

// pack two bf16 (low half = even-k element)
__device__ __forceinline__ unsigned pack2(unsigned short e, unsigned short o) {
    return (unsigned)e | ((unsigned)o << 16);
}

#define WS 104   // 104 % 32 == 8  -> q4*WS + g hits 32 distinct banks
#define XS 136   // 136 % 32 == 8  -> same property

__device__ __forceinline__ void gemm_tc_body(
    const float* __restrict__ Wsrc,   // [96][96] row-major
    const float* __restrict__ Xb,     // rows N floats apart, 128-px window
    float* __restrict__ Ob)           // rows N floats apart
{
    // per 16-k chunk: 8 k-pairs x (96 outs | 128 px), hi and lo parts
    __shared__ unsigned Wpk[8 * WS], Wpl[8 * WS];
    __shared__ unsigned Xph[8 * XS], Xpl[8 * XS];

    int tid  = threadIdx.x;
    int lane = tid & 31, wid = tid >> 5;
    int warpM = wid >> 2, warpN = wid & 3;
    int m0 = warpM * 48, n0 = warpN * 32;
    int g = lane >> 2, q4 = lane & 3;

    float acc[3][4][4] = {};

    for (int kk = 0; kk < 96; kk += 16) {
        // --- stage W chunk: Wp*[t][o] = pack(W[o][kk+2t], W[o][kk+2t+1]) ---
        for (int i = tid; i < 768; i += 256) {
            int t = i / 96, o = i - t * 96;
            float2 w2 = *(const float2*)(Wsrc + o * 96 + kk + 2 * t);
            unsigned short he, le, ho, lo;
            split_bf16(w2.x, he, le);
            split_bf16(w2.y, ho, lo);
            Wpk[t * WS + o] = pack2(he, ho);
            Wpl[t * WS + o] = pack2(le, lo);
        }
        // --- stage X chunk: Xp*[t][px] = pack(X[kk+2t][px], X[kk+2t+1][px]) ---
        {
            int t = tid >> 5, c4 = tid & 31;           // 8 x 32 = 256 exactly
            float4 x0 = *(const float4*)(Xb + (long)(kk + 2 * t) * N + c4 * 4);
            float4 x1 = *(const float4*)(Xb + (long)(kk + 2 * t + 1) * N + c4 * 4);
            uint4 hv, lv;
            unsigned short h0, l0, h1, l1;
            split_bf16(x0.x, h0, l0); split_bf16(x1.x, h1, l1);
            hv.x = pack2(h0, h1); lv.x = pack2(l0, l1);
            split_bf16(x0.y, h0, l0); split_bf16(x1.y, h1, l1);
            hv.y = pack2(h0, h1); lv.y = pack2(l0, l1);
            split_bf16(x0.z, h0, l0); split_bf16(x1.z, h1, l1);
            hv.z = pack2(h0, h1); lv.z = pack2(l0, l1);
            split_bf16(x0.w, h0, l0); split_bf16(x1.w, h1, l1);
            hv.w = pack2(h0, h1); lv.w = pack2(l0, l1);
            *(uint4*)(Xph + t * XS + c4 * 4) = hv;
            *(uint4*)(Xpl + t * XS + c4 * 4) = lv;
        }
        __syncthreads();

        // --- one m16n8k16 k-step consumes the whole 16-k chunk ---
        unsigned Ah[3][4], Al[3][4];
#pragma unroll
        for (int mi = 0; mi < 3; mi++) {
            int m = m0 + mi * 16 + g;
            int r0 = q4 * WS, r1 = (q4 + 4) * WS;
            Ah[mi][0] = Wpk[r0 + m]; Ah[mi][1] = Wpk[r0 + m + 8];
            Ah[mi][2] = Wpk[r1 + m]; Ah[mi][3] = Wpk[r1 + m + 8];
            Al[mi][0] = Wpl[r0 + m]; Al[mi][1] = Wpl[r0 + m + 8];
            Al[mi][2] = Wpl[r1 + m]; Al[mi][3] = Wpl[r1 + m + 8];
        }
#pragma unroll
        for (int ni = 0; ni < 4; ni++) {
            int n = n0 + ni * 8 + g;
            unsigned bh[2], bl[2];
            bh[0] = Xph[q4 * XS + n]; bh[1] = Xph[(q4 + 4) * XS + n];
            bl[0] = Xpl[q4 * XS + n]; bl[1] = Xpl[(q4 + 4) * XS + n];
#pragma unroll
            for (int mi = 0; mi < 3; mi++) {
                mma_bf16(acc[mi][ni], Ah[mi], bh);
                mma_bf16(acc[mi][ni], Ah[mi], bl);
                mma_bf16(acc[mi][ni], Al[mi], bh);
            }
        }
        __syncthreads();
    }

    // --- epilogue: c0,c1 at (row, 2q4), c2,c3 at (row+8, 2q4) ---
#pragma unroll
    for (int mi = 0; mi < 3; mi++) {
        int row = m0 + mi * 16 + g;
#pragma unroll
        for (int ni = 0; ni < 4; ni++) {
            int col = n0 + ni * 8 + 2 * q4;
            *(float2*)(Ob + (long)row * N + col) =
                make_float2(acc[mi][ni][0], acc[mi][ni][1]);
            *(float2*)(Ob + (long)(row + 8) * N + col) =
                make_float2(acc[mi][ni][2], acc[mi][ni][3]);
        }
    }
}

// conv1x1 into g_P at channel offset oBase. grid (512, yGroups, BATCH)
__global__ __launch_bounds__(256) void gemm_in_tc(
    const float* __restrict__ W, const float* __restrict__ X, int oBase)
{
    const float* Wsrc = W + blockIdx.y * 9216;
    const float* Xb   = X + (long)blockIdx.z * DIM * N + blockIdx.x * 128;
    float* Ob = g_P + ((long)blockIdx.z * TOT + oBase + blockIdx.y * 96) * N
              + blockIdx.x * 128;
    gemm_tc_body(Wsrc, Xb, Ob);
}

// final: out = M[b] @ v, v = g_DW channels 96..191. grid (512, 1, BATCH)
__global__ __launch_bounds__(256) void gemm_out_tc(float* __restrict__ out)
{
    const float* Wsrc = g_M + (long)blockIdx.z * DIM * DIM;
    const float* Xb   = g_DW + ((long)blockIdx.z * TOT + DIM) * N + blockIdx.x * 128;
    float* Ob = out + (long)blockIdx.z * DIM * N + blockIdx.x * 128;
    gemm_tc_body(Wsrc, Xb, Ob);
}

// ---------------- K2: depthwise 3x3 + norm sumsq, smem-staged ----------------
// grid (32 stripes of 8 rows, 288 channels, 4 batches), block 256.
// Each global input row is read exactly once per block (coalesced float4);
// all neighborhood reads come from padded smem (zero guard cols/rows).
__global__ __launch_bounds__(256) void dwconv_kernel(
    const float* __restrict__ kv_dw, const float* __restrict__ q_dw)
{
    __shared__ float S[10][264];   // rows y0-1..y0+8, cols at +4, guards zeroed
    int tid = threadIdx.x;
    int ch = blockIdx.y, b = blockIdx.z;
    int y0 = blockIdx.x * 8;
    const float* in  = g_P  + ((long)b * TOT + ch) * N;
    float*       out = g_DW + ((long)b * TOT + ch) * N;
    const float* wp = (ch < 192) ? (kv_dw + ch * 9) : (q_dw + (ch - 192) * 9);
    float w[9];
#pragma unroll
    for (int i = 0; i < 9; i++) w[i] = __ldg(wp + i);

    // load 10 rows x 64 float4
    for (int i = tid; i < 640; i += 256) {
        int r = i >> 6, c4 = i & 63;
        int y = y0 + r - 1;
        float4 v = (y >= 0 && y < 256)
                 ? *(const float4*)(in + y * 256 + c4 * 4)
                 : make_float4(0.f, 0.f, 0.f, 0.f);
        *(float4*)&S[r][4 + c4 * 4] = v;
    }
    // zero horizontal guard columns (cols 0..3 and 260..263, 10 rows)
    if (tid < 80) {
        int r = tid >> 3, c = tid & 7;
        S[r][(c < 4) ? c : c + 256] = 0.f;
    }
    __syncthreads();

    int ry = tid >> 5;          // warp id = output row within stripe
    int lane = tid & 31;
    float s = 0.f;
#pragma unroll
    for (int gi = 0; gi < 2; gi++) {
        int px = lane * 8 + gi * 4;
        float o0 = 0.f, o1 = 0.f, o2 = 0.f, o3 = 0.f;
#pragma unroll
        for (int d = 0; d < 3; d++) {
            const float* r = &S[ry + d][4 + px];
            float4 c = *(const float4*)r;
            float lf = r[-1], rt = r[4];
            float w0 = w[d * 3], w1 = w[d * 3 + 1], w2 = w[d * 3 + 2];
            o0 += w0 * lf  + w1 * c.x + w2 * c.y;
            o1 += w0 * c.x + w1 * c.y + w2 * c.z;
            o2 += w0 * c.y + w1 * c.z + w2 * c.w;
            o3 += w0 * c.z + w1 * c.w + w2 * rt;
        }
        *(float4*)(out + (y0 + ry) * 256 + px) = make_float4(o0, o1, o2, o3);
        s += o0 * o0 + o1 * o1 + o2 * o2 + o3 * o3;
    }

    // accumulate sum-of-squares for q / k channel norms
#pragma unroll
    for (int off = 16; off; off >>= 1) s += __shfl_down_sync(0xffffffffu, s, off);
    __shared__ float red[8];
    if ((tid & 31) == 0) red[tid >> 5] = s;
    __syncthreads();
    if (tid == 0) {
        float t = 0.f;
#pragma unroll
        for (int i = 0; i < 8; i++) t += red[i];
        if (ch < 96)        atomicAdd(&g_kn2[b * DIM + ch], t);
        else if (ch >= 192) atomicAdd(&g_qn2[b * DIM + ch - 192], t);
    }
}

// ---------------- K3: Gram matrix G[b][h] = q_raw @ k_raw^T (split-K) -------
__global__ __launch_bounds__(256) void gram_kernel()
{
    __shared__ float Qt[48 * 68];
    __shared__ float Kt[48 * 68];
    int tid = threadIdx.x;
    int b = blockIdx.z, h = blockIdx.y;
    int pix0 = blockIdx.x * 2048;
    const float* Qb = g_DW + ((long)b * TOT + 192 + h * CPH) * N;
    const float* Kb = g_DW + ((long)b * TOT + h * CPH) * N;

    float acc[3][3] = {};
    int tr = tid >> 4, tc = tid & 15;

    for (int t = 0; t < 32; t++) {
        int p0 = pix0 + t * 64;
        for (int i = tid; i < 768; i += 256) {
            int r = i >> 4, c4 = i & 15;
            *(float4*)(Qt + r * 68 + c4 * 4) = *(const float4*)(Qb + (long)r * N + p0 + c4 * 4);
            *(float4*)(Kt + r * 68 + c4 * 4) = *(const float4*)(Kb + (long)r * N + p0 + c4 * 4);
        }
        __syncthreads();
#pragma unroll 2
        for (int p = 0; p < 64; p += 4) {
            float4 q0 = *(float4*)(Qt + (tr * 3 + 0) * 68 + p);
            float4 q1 = *(float4*)(Qt + (tr * 3 + 1) * 68 + p);
            float4 q2 = *(float4*)(Qt + (tr * 3 + 2) * 68 + p);
            float4 k0 = *(float4*)(Kt + (tc * 3 + 0) * 68 + p);
            float4 k1 = *(float4*)(Kt + (tc * 3 + 1) * 68 + p);
            float4 k2 = *(float4*)(Kt + (tc * 3 + 2) * 68 + p);
            acc[0][0] += q0.x*k0.x + q0.y*k0.y + q0.z*k0.z + q0.w*k0.w;
            acc[0][1] += q0.x*k1.x + q0.y*k1.y + q0.z*k1.z + q0.w*k1.w;
            acc[0][2] += q0.x*k2.x + q0.y*k2.y + q0.z*k2.z + q0.w*k2.w;
            acc[1][0] += q1.x*k0.x + q1.y*k0.y + q1.z*k0.z + q1.w*k0.w;
            acc[1][1] += q1.x*k1.x + q1.y*k1.y + q1.z*k1.z + q1.w*k1.w;
            acc[1][2] += q1.x*k2.x + q1.y*k2.y + q1.z*k2.z + q1.w*k2.w;
            acc[2][0] += q2.x*k0.x + q2.y*k0.y + q2.z*k0.z + q2.w*k0.w;
            acc[2][1] += q2.x*k1.x + q2.y*k1.y + q2.z*k1.z + q2.w*k1.w;
            acc[2][2] += q2.x*k2.x + q2.y*k2.y + q2.z*k2.z + q2.w*k2.w;
        }
        __syncthreads();
    }
    float* Gp = g_G + (long)(b * HEADS + h) * CPH * CPH;
#pragma unroll
    for (int i = 0; i < 3; i++)
#pragma unroll
        for (int j = 0; j < 3; j++)
            atomicAdd(&Gp[(tr * 3 + i) * CPH + tc * 3 + j], acc[i][j]);
}

// ---------------- K4: normalize, 4x top-k softmax, fold proj into M ---------
__global__ __launch_bounds__(256) void attn_kernel(
    const float* __restrict__ temp, const float* __restrict__ proj_w,
    const float* __restrict__ a1, const float* __restrict__ a2,
    const float* __restrict__ a3, const float* __restrict__ a4)
{
    int b = blockIdx.x >> 1;
    int h = blockIdx.x & 1;
    int tid = threadIdx.x;
    __shared__ float attnS[48 * 49];
    __shared__ float WcS[48 * 49];
    __shared__ float nqS[48], nkS[48];

    if (tid < 48) {
        nqS[tid] = fmaxf(sqrtf(g_qn2[b * DIM + h * CPH + tid]), 1e-12f);
        nkS[tid] = fmaxf(sqrtf(g_kn2[b * DIM + h * CPH + tid]), 1e-12f);
    }
    __syncthreads();

    float tp = temp[h];
    const float* Gp = g_G + (long)(b * HEADS + h) * CPH * CPH;
    for (int i = tid; i < 48 * 48; i += 256) {
        int c = i / 48, d = i % 48;
        attnS[c * 49 + d] = Gp[c * 48 + d] / (nqS[c] * nkS[d]) * tp;
    }
    __syncthreads();

    if (tid < 48) {
        const float* row = attnS + tid * 49;
        float mx = row[0];
        for (int d = 1; d < 48; d++) mx = fmaxf(mx, row[d]);
        float s0 = 0.f, s1 = 0.f, s2 = 0.f, s3 = 0.f;
        for (int d = 0; d < 48; d++) {
            float a = row[d];
            int r = 0;
            for (int dd = 0; dd < 48; dd++) r += (row[dd] > a);
            float e = expf(a - mx);
            if (r < 24) s0 += e;
            if (r < 32) s1 += e;
            if (r < 36) s2 += e;
            if (r < 38) s3 += e;
        }
        float f0 = a1[0] / s0, f1 = a2[0] / s1, f2 = a3[0] / s2, f3 = a4[0] / s3;
        for (int d = 0; d < 48; d++) {
            float a = row[d];
            int r = 0;
            for (int dd = 0; dd < 48; dd++) r += (row[dd] > a);
            float e = expf(a - mx);
            float wv = e * ((r < 24 ? f0 : 0.f) + (r < 32 ? f1 : 0.f)
                          + (r < 36 ? f2 : 0.f) + (r < 38 ? f3 : 0.f));
            WcS[tid * 49 + d] = wv;
        }
    }
    __syncthreads();

    for (int i = tid; i < 96 * 48; i += 256) {
        int o = i / 48, d = i % 48;
        float s = 0.f;
        const float* pw = proj_w + o * DIM + h * CPH;
        for (int c = 0; c < 48; c++) s += pw[c] * WcS[c * 49 + d];
        g_M[(long)(b * DIM + o) * DIM + h * CPH + d] = s;
    }
}

// --------------------------------- launch -----------------------------------
extern "C" void kernel_launch(void* const* d_in, const int* in_sizes, int n_in,
                              void* d_out, int out_size)
{
    const float* x      = (const float*)d_in[0];
    const float* y      = (const float*)d_in[1];
    const float* temp   = (const float*)d_in[2];
    const float* kv_w   = (const float*)d_in[3];
    const float* kv_dw  = (const float*)d_in[4];
    const float* q_w    = (const float*)d_in[5];
    const float* q_dw   = (const float*)d_in[6];
    const float* proj_w = (const float*)d_in[7];
    const float* a1     = (const float*)d_in[8];
    const float* a2     = (const float*)d_in[9];
    const float* a3     = (const float*)d_in[10];
    const float* a4     = (const float*)d_in[11];
    float* out = (float*)d_out;

    zero_kernel<<<72, 256>>>();

    // conv1x1 (tensor cores, bf16x3): kv from x (ch 0..191), q from y (ch 192..287)
    gemm_in_tc<<<dim3(512, 2, BATCH), 256>>>(kv_w, x, 0);
    gemm_in_tc<<<dim3(512, 1, BATCH), 256>>>(q_w,  y, 192);

    // depthwise 3x3 on all 288 channels + q/k norm accumulation (smem-staged)
    dwconv_kernel<<<dim3(32, TOT, BATCH), 256>>>(kv_dw, q_dw);

    // Gram matrices (split-K with atomics, fp32)
    gram_kernel<<<dim3(32, HEADS, BATCH), 256>>>();

    // tiny: normalize + top-k softmaxes + fold proj -> per-batch 96x96 M
    attn_kernel<<<8, 256>>>(temp, proj_w, a1, a2, a3, a4);

    // final = M @ v (tensor cores, bf16x3)
    gemm_out_tc<<<dim3(512, 1, BATCH), 256>>>(out);
}

// round 12
// speedup vs baseline: 1.4324x; 1.2206x over previous
#include <cuda_runtime.h>
#include <cuda_bf16.h>
#include <math.h>

#define N      65536
#define BATCH  4
#define DIM    96
#define TOT    288     // 192 kv channels + 96 q channels
#define HEADS  2
#define CPH    48

// ---------------- scratch (static device globals; no allocs) ----------------
__device__ float g_P [BATCH * TOT * N];   // conv1x1 outputs  [b][288][N]
__device__ float g_DW[BATCH * TOT * N];   // dwconv outputs   [b][288][N]
__device__ float g_G  [BATCH * HEADS * CPH * CPH];
__device__ float g_qn2[BATCH * DIM];
__device__ float g_kn2[BATCH * DIM];
__device__ float g_M  [BATCH * DIM * DIM];

// ---------------- K0: zero the atomically-accumulated state ----------------
__global__ void zero_kernel() {
    int i = blockIdx.x * 256 + threadIdx.x;
    if (i < BATCH * HEADS * CPH * CPH) g_G[i] = 0.f;
    if (i < BATCH * DIM) { g_qn2[i] = 0.f; g_kn2[i] = 0.f; }
}

// =====================  bf16x3 tensor-core GEMM (double-buffered) ===========
// C[96][128] += W[96][96] * X[96][128-px window], near-fp32 via 3-term bf16
// split: A*B ~= Ah*Bh + Ah*Bl + Al*Bh  (residual ~2^-18).
// Block: 256 threads = 8 warps (2x4); warp tile 48(M) x 32(N).
// Next k-chunk's global loads are issued right after the staging sync so
// their latency overlaps the mma compute.

__device__ __forceinline__ void mma_bf16(float* c, const unsigned* a, const unsigned* b) {
    asm volatile(
        "mma.sync.aligned.m16n8k16.row.col.f32.bf16.bf16.f32 "
        "{%0,%1,%2,%3}, {%4,%5,%6,%7}, {%8,%9}, {%0,%1,%2,%3};"
        : "+f"(c[0]), "+f"(c[1]), "+f"(c[2]), "+f"(c[3])
        : "r"(a[0]), "r"(a[1]), "r"(a[2]), "r"(a[3]), "r"(b[0]), "r"(b[1]));
}

__device__ __forceinline__ void split_bf16(float v, unsigned short& h, unsigned short& l) {
    __nv_bfloat16 bh = __float2bfloat16(v);           // rn
    float r = v - __bfloat162float(bh);               // exact
    __nv_bfloat16 bl = __float2bfloat16(r);
    h = __bfloat16_as_ushort(bh);
    l = __bfloat16_as_ushort(bl);
}

// pack two bf16 (low half = even-k element)
__device__ __forceinline__ unsigned pack2(unsigned short e, unsigned short o) {
    return (unsigned)e | ((unsigned)o << 16);
}

#define WS 104   // 104 % 32 == 8  -> q4*WS + g hits 32 distinct banks
#define XS 136   // 136 % 32 == 8  -> same property

__device__ __forceinline__ void gemm_tc_body(
    const float* __restrict__ Wsrc,   // [96][96] row-major
    const float* __restrict__ Xb,     // rows N floats apart, 128-px window
    float* __restrict__ Ob)           // rows N floats apart
{
    // per 16-k chunk: 8 k-pairs x (96 outs | 128 px), hi and lo parts
    __shared__ unsigned Wpk[8 * WS], Wpl[8 * WS];
    __shared__ unsigned Xph[8 * XS], Xpl[8 * XS];

    int tid  = threadIdx.x;
    int lane = tid & 31, wid = tid >> 5;
    int warpM = wid >> 2, warpN = wid & 3;
    int m0 = warpM * 48, n0 = warpN * 32;
    int g = lane >> 2, q4 = lane & 3;

    float acc[3][4][4] = {};

    // prefetch registers (chunk 0)
    float2 wpre[3];
    float4 xpre0, xpre1;
    int xt = tid >> 5, xc4 = tid & 31;
#pragma unroll
    for (int j = 0; j < 3; j++) {
        int i = tid + j * 256;
        int t = i / 96, o = i - t * 96;
        wpre[j] = *(const float2*)(Wsrc + o * 96 + 2 * t);
    }
    xpre0 = *(const float4*)(Xb + (long)(2 * xt) * N + xc4 * 4);
    xpre1 = *(const float4*)(Xb + (long)(2 * xt + 1) * N + xc4 * 4);

    for (int kk = 0; kk < 96; kk += 16) {
        // --- convert + store staged chunk (from prefetch regs) ---
#pragma unroll
        for (int j = 0; j < 3; j++) {
            int i = tid + j * 256;
            int t = i / 96, o = i - t * 96;
            unsigned short he, le, ho, lo;
            split_bf16(wpre[j].x, he, le);
            split_bf16(wpre[j].y, ho, lo);
            Wpk[t * WS + o] = pack2(he, ho);
            Wpl[t * WS + o] = pack2(le, lo);
        }
        {
            uint4 hv, lv;
            unsigned short h0, l0, h1, l1;
            split_bf16(xpre0.x, h0, l0); split_bf16(xpre1.x, h1, l1);
            hv.x = pack2(h0, h1); lv.x = pack2(l0, l1);
            split_bf16(xpre0.y, h0, l0); split_bf16(xpre1.y, h1, l1);
            hv.y = pack2(h0, h1); lv.y = pack2(l0, l1);
            split_bf16(xpre0.z, h0, l0); split_bf16(xpre1.z, h1, l1);
            hv.z = pack2(h0, h1); lv.z = pack2(l0, l1);
            split_bf16(xpre0.w, h0, l0); split_bf16(xpre1.w, h1, l1);
            hv.w = pack2(h0, h1); lv.w = pack2(l0, l1);
            *(uint4*)(Xph + xt * XS + xc4 * 4) = hv;
            *(uint4*)(Xpl + xt * XS + xc4 * 4) = lv;
        }
        __syncthreads();

        // --- issue next chunk's global loads (latency overlaps mma) ---
        if (kk + 16 < 96) {
#pragma unroll
            for (int j = 0; j < 3; j++) {
                int i = tid + j * 256;
                int t = i / 96, o = i - t * 96;
                wpre[j] = *(const float2*)(Wsrc + o * 96 + (kk + 16) + 2 * t);
            }
            xpre0 = *(const float4*)(Xb + (long)(kk + 16 + 2 * xt) * N + xc4 * 4);
            xpre1 = *(const float4*)(Xb + (long)(kk + 16 + 2 * xt + 1) * N + xc4 * 4);
        }

        // --- one m16n8k16 k-step consumes the whole 16-k chunk ---
        unsigned Ah[3][4], Al[3][4];
#pragma unroll
        for (int mi = 0; mi < 3; mi++) {
            int m = m0 + mi * 16 + g;
            int r0 = q4 * WS, r1 = (q4 + 4) * WS;
            Ah[mi][0] = Wpk[r0 + m]; Ah[mi][1] = Wpk[r0 + m + 8];
            Ah[mi][2] = Wpk[r1 + m]; Ah[mi][3] = Wpk[r1 + m + 8];
            Al[mi][0] = Wpl[r0 + m]; Al[mi][1] = Wpl[r0 + m + 8];
            Al[mi][2] = Wpl[r1 + m]; Al[mi][3] = Wpl[r1 + m + 8];
        }
#pragma unroll
        for (int ni = 0; ni < 4; ni++) {
            int n = n0 + ni * 8 + g;
            unsigned bh[2], bl[2];
            bh[0] = Xph[q4 * XS + n]; bh[1] = Xph[(q4 + 4) * XS + n];
            bl[0] = Xpl[q4 * XS + n]; bl[1] = Xpl[(q4 + 4) * XS + n];
#pragma unroll
            for (int mi = 0; mi < 3; mi++) {
                mma_bf16(acc[mi][ni], Ah[mi], bh);
                mma_bf16(acc[mi][ni], Ah[mi], bl);
                mma_bf16(acc[mi][ni], Al[mi], bh);
            }
        }
        __syncthreads();
    }

    // --- epilogue: c0,c1 at (row, 2q4), c2,c3 at (row+8, 2q4) ---
#pragma unroll
    for (int mi = 0; mi < 3; mi++) {
        int row = m0 + mi * 16 + g;
#pragma unroll
        for (int ni = 0; ni < 4; ni++) {
            int col = n0 + ni * 8 + 2 * q4;
            *(float2*)(Ob + (long)row * N + col) =
                make_float2(acc[mi][ni][0], acc[mi][ni][1]);
            *(float2*)(Ob + (long)(row + 8) * N + col) =
                make_float2(acc[mi][ni][2], acc[mi][ni][3]);
        }
    }
}

// conv1x1 into g_P at channel offset oBase. grid (512, yGroups, BATCH)
__global__ __launch_bounds__(256) void gemm_in_tc(
    const float* __restrict__ W, const float* __restrict__ X, int oBase)
{
    const float* Wsrc = W + blockIdx.y * 9216;
    const float* Xb   = X + (long)blockIdx.z * DIM * N + blockIdx.x * 128;
    float* Ob = g_P + ((long)blockIdx.z * TOT + oBase + blockIdx.y * 96) * N
              + blockIdx.x * 128;
    gemm_tc_body(Wsrc, Xb, Ob);
}

// final: out = M[b] @ v, v = g_DW channels 96..191. grid (512, 1, BATCH)
__global__ __launch_bounds__(256) void gemm_out_tc(float* __restrict__ out)
{
    const float* Wsrc = g_M + (long)blockIdx.z * DIM * DIM;
    const float* Xb   = g_DW + ((long)blockIdx.z * TOT + DIM) * N + blockIdx.x * 128;
    float* Ob = out + (long)blockIdx.z * DIM * N + blockIdx.x * 128;
    gemm_tc_body(Wsrc, Xb, Ob);
}

// ---------------- K2: depthwise 3x3 (same, zero pad) + norm sumsq -----------
// (reverted to the measured-good round-2 version: 160.9us, no smem staging)
// grid (64 row-chunks, 288 channels, 4 batches), block 256.
__global__ __launch_bounds__(256) void dwconv_kernel(
    const float* __restrict__ kv_dw, const float* __restrict__ q_dw)
{
    int tid = threadIdx.x;
    int ch = blockIdx.y, b = blockIdx.z;
    int y0 = blockIdx.x * 4;
    const float* in  = g_P  + ((long)b * TOT + ch) * N;
    float*       out = g_DW + ((long)b * TOT + ch) * N;
    const float* wp = (ch < 192) ? (kv_dw + ch * 9) : (q_dw + (ch - 192) * 9);
    float w[9];
#pragma unroll
    for (int i = 0; i < 9; i++) w[i] = __ldg(wp + i);

    int ry = tid >> 6;
    int px = (tid & 63) * 4;
    int yy = y0 + ry;
    float o0 = 0.f, o1 = 0.f, o2 = 0.f, o3 = 0.f;
#pragma unroll
    for (int dy = -1; dy <= 1; dy++) {
        int ys = yy + dy;
        if (ys < 0 || ys > 255) continue;
        const float* r = in + ys * 256 + px;
        float4 c = *(const float4*)r;
        float lf = (px > 0)   ? r[-1] : 0.f;
        float rt = (px < 252) ? r[4]  : 0.f;
        float w0 = w[(dy + 1) * 3], w1 = w[(dy + 1) * 3 + 1], w2 = w[(dy + 1) * 3 + 2];
        o0 += w0 * lf  + w1 * c.x + w2 * c.y;
        o1 += w0 * c.x + w1 * c.y + w2 * c.z;
        o2 += w0 * c.y + w1 * c.z + w2 * c.w;
        o3 += w0 * c.z + w1 * c.w + w2 * rt;
    }
    *(float4*)(out + yy * 256 + px) = make_float4(o0, o1, o2, o3);

    float s = o0 * o0 + o1 * o1 + o2 * o2 + o3 * o3;
#pragma unroll
    for (int off = 16; off; off >>= 1) s += __shfl_down_sync(0xffffffffu, s, off);
    __shared__ float red[8];
    if ((tid & 31) == 0) red[tid >> 5] = s;
    __syncthreads();
    if (tid == 0) {
        float t = 0.f;
#pragma unroll
        for (int i = 0; i < 8; i++) t += red[i];
        if (ch < 96)        atomicAdd(&g_kn2[b * DIM + ch], t);
        else if (ch >= 192) atomicAdd(&g_qn2[b * DIM + ch - 192], t);
    }
}

// ---------------- K3: Gram matrix G[b][h] = q_raw @ k_raw^T (split-K, DB) ---
__global__ __launch_bounds__(256) void gram_kernel()
{
    __shared__ float Qt[48 * 68];
    __shared__ float Kt[48 * 68];
    int tid = threadIdx.x;
    int b = blockIdx.z, h = blockIdx.y;
    int pix0 = blockIdx.x * 2048;
    const float* Qb = g_DW + ((long)b * TOT + 192 + h * CPH) * N;
    const float* Kb = g_DW + ((long)b * TOT + h * CPH) * N;

    float acc[3][3] = {};
    int tr = tid >> 4, tc = tid & 15;

    // prefetch tile 0
    float4 qpre[3], kpre[3];
#pragma unroll
    for (int j = 0; j < 3; j++) {
        int i = tid + j * 256;
        int r = i >> 4, c4 = i & 15;
        qpre[j] = *(const float4*)(Qb + (long)r * N + pix0 + c4 * 4);
        kpre[j] = *(const float4*)(Kb + (long)r * N + pix0 + c4 * 4);
    }

    for (int t = 0; t < 32; t++) {
#pragma unroll
        for (int j = 0; j < 3; j++) {
            int i = tid + j * 256;
            int r = i >> 4, c4 = i & 15;
            *(float4*)(Qt + r * 68 + c4 * 4) = qpre[j];
            *(float4*)(Kt + r * 68 + c4 * 4) = kpre[j];
        }
        __syncthreads();

        if (t + 1 < 32) {
            int p1 = pix0 + (t + 1) * 64;
#pragma unroll
            for (int j = 0; j < 3; j++) {
                int i = tid + j * 256;
                int r = i >> 4, c4 = i & 15;
                qpre[j] = *(const float4*)(Qb + (long)r * N + p1 + c4 * 4);
                kpre[j] = *(const float4*)(Kb + (long)r * N + p1 + c4 * 4);
            }
        }

#pragma unroll 2
        for (int p = 0; p < 64; p += 4) {
            float4 q0 = *(float4*)(Qt + (tr * 3 + 0) * 68 + p);
            float4 q1 = *(float4*)(Qt + (tr * 3 + 1) * 68 + p);
            float4 q2 = *(float4*)(Qt + (tr * 3 + 2) * 68 + p);
            float4 k0 = *(float4*)(Kt + (tc * 3 + 0) * 68 + p);
            float4 k1 = *(float4*)(Kt + (tc * 3 + 1) * 68 + p);
            float4 k2 = *(float4*)(Kt + (tc * 3 + 2) * 68 + p);
            acc[0][0] += q0.x*k0.x + q0.y*k0.y + q0.z*k0.z + q0.w*k0.w;
            acc[0][1] += q0.x*k1.x + q0.y*k1.y + q0.z*k1.z + q0.w*k1.w;
            acc[0][2] += q0.x*k2.x + q0.y*k2.y + q0.z*k2.z + q0.w*k2.w;
            acc[1][0] += q1.x*k0.x + q1.y*k0.y + q1.z*k0.z + q1.w*k0.w;
            acc[1][1] += q1.x*k1.x + q1.y*k1.y + q1.z*k1.z + q1.w*k1.w;
            acc[1][2] += q1.x*k2.x + q1.y*k2.y + q1.z*k2.z + q1.w*k2.w;
            acc[2][0] += q2.x*k0.x + q2.y*k0.y + q2.z*k0.z + q2.w*k0.w;
            acc[2][1] += q2.x*k1.x + q2.y*k1.y + q2.z*k1.z + q2.w*k1.w;
            acc[2][2] += q2.x*k2.x + q2.y*k2.y + q2.z*k2.z + q2.w*k2.w;
        }
        __syncthreads();
    }
    float* Gp = g_G + (long)(b * HEADS + h) * CPH * CPH;
#pragma unroll
    for (int i = 0; i < 3; i++)
#pragma unroll
        for (int j = 0; j < 3; j++)
            atomicAdd(&Gp[(tr * 3 + i) * CPH + tc * 3 + j], acc[i][j]);
}

// ---------------- K4: normalize, 4x top-k softmax, fold proj into M ---------
// grid 8 = (b,h), block 256. Rank/exp work parallelized across all threads.
__global__ __launch_bounds__(256) void attn_kernel(
    const float* __restrict__ temp, const float* __restrict__ proj_w,
    const float* __restrict__ a1, const float* __restrict__ a2,
    const float* __restrict__ a3, const float* __restrict__ a4)
{
    int b = blockIdx.x >> 1;
    int h = blockIdx.x & 1;
    int tid = threadIdx.x;
    __shared__ float attnS[48 * 49];
    __shared__ float eS[48 * 49];
    __shared__ float rkS[48 * 49];
    __shared__ float WcS[48 * 49];
    __shared__ float nqS[48], nkS[48], mxS[48];
    __shared__ float sS[4 * 48];
    __shared__ float fS[4 * 48];

    if (tid < 48) {
        nqS[tid] = fmaxf(sqrtf(g_qn2[b * DIM + h * CPH + tid]), 1e-12f);
        nkS[tid] = fmaxf(sqrtf(g_kn2[b * DIM + h * CPH + tid]), 1e-12f);
    }
    if (tid < 192) sS[tid] = 0.f;
    __syncthreads();

    float tp = temp[h];
    const float* Gp = g_G + (long)(b * HEADS + h) * CPH * CPH;
    for (int i = tid; i < 48 * 48; i += 256) {
        int c = i / 48, d = i % 48;
        attnS[c * 49 + d] = Gp[c * 48 + d] / (nqS[c] * nkS[d]) * tp;
    }
    __syncthreads();

    if (tid < 48) {
        const float* row = attnS + tid * 49;
        float mx = row[0];
        for (int d = 1; d < 48; d++) mx = fmaxf(mx, row[d]);
        mxS[tid] = mx;
    }
    __syncthreads();

    // ranks + exp + partial sums, parallel over all 2304 entries
    for (int i = tid; i < 48 * 48; i += 256) {
        int c = i / 48, d = i % 48;
        const float* row = attnS + c * 49;
        float a = row[d];
        int r = 0;
        for (int dd = 0; dd < 48; dd++) r += (row[dd] > a);
        float e = expf(a - mxS[c]);
        eS[c * 49 + d]  = e;
        rkS[c * 49 + d] = (float)r;
        if (r < 24) atomicAdd(&sS[0 * 48 + c], e);
        if (r < 32) atomicAdd(&sS[1 * 48 + c], e);
        if (r < 36) atomicAdd(&sS[2 * 48 + c], e);
        if (r < 38) atomicAdd(&sS[3 * 48 + c], e);
    }
    __syncthreads();

    if (tid < 192) {
        int j = tid / 48, c = tid % 48;
        float aj = (j == 0) ? a1[0] : (j == 1) ? a2[0] : (j == 2) ? a3[0] : a4[0];
        fS[j * 48 + c] = aj / sS[j * 48 + c];
    }
    __syncthreads();

    for (int i = tid; i < 48 * 48; i += 256) {
        int c = i / 48, d = i % 48;
        float e = eS[c * 49 + d];
        int r = (int)rkS[c * 49 + d];
        float wv = e * ((r < 24 ? fS[0 * 48 + c] : 0.f) + (r < 32 ? fS[1 * 48 + c] : 0.f)
                      + (r < 36 ? fS[2 * 48 + c] : 0.f) + (r < 38 ? fS[3 * 48 + c] : 0.f));
        WcS[c * 49 + d] = wv;
    }
    __syncthreads();

    // M[b][o][h*48+d] = sum_c proj_w[o][h*48+c] * Wc[c][d]
    for (int i = tid; i < 96 * 48; i += 256) {
        int o = i / 48, d = i % 48;
        float s = 0.f;
        const float* pw = proj_w + o * DIM + h * CPH;
        for (int c = 0; c < 48; c++) s += pw[c] * WcS[c * 49 + d];
        g_M[(long)(b * DIM + o) * DIM + h * CPH + d] = s;
    }
}

// --------------------------------- launch -----------------------------------
extern "C" void kernel_launch(void* const* d_in, const int* in_sizes, int n_in,
                              void* d_out, int out_size)
{
    const float* x      = (const float*)d_in[0];
    const float* y      = (const float*)d_in[1];
    const float* temp   = (const float*)d_in[2];
    const float* kv_w   = (const float*)d_in[3];
    const float* kv_dw  = (const float*)d_in[4];
    const float* q_w    = (const float*)d_in[5];
    const float* q_dw   = (const float*)d_in[6];
    const float* proj_w = (const float*)d_in[7];
    const float* a1     = (const float*)d_in[8];
    const float* a2     = (const float*)d_in[9];
    const float* a3     = (const float*)d_in[10];
    const float* a4     = (const float*)d_in[11];
    float* out = (float*)d_out;

    zero_kernel<<<72, 256>>>();

    // conv1x1 (tensor cores, bf16x3, double-buffered)
    gemm_in_tc<<<dim3(512, 2, BATCH), 256>>>(kv_w, x, 0);
    gemm_in_tc<<<dim3(512, 1, BATCH), 256>>>(q_w,  y, 192);

    // depthwise 3x3 on all 288 channels + q/k norm accumulation
    dwconv_kernel<<<dim3(64, TOT, BATCH), 256>>>(kv_dw, q_dw);

    // Gram matrices (split-K with atomics, double-buffered)
    gram_kernel<<<dim3(32, HEADS, BATCH), 256>>>();

    // normalize + top-k softmaxes + fold proj -> per-batch 96x96 M
    attn_kernel<<<8, 256>>>(temp, proj_w, a1, a2, a3, a4);

    // final = M @ v (tensor cores, bf16x3, double-buffered)
    gemm_out_tc<<<dim3(512, 1, BATCH), 256>>>(out);
}